// round 2
// baseline (speedup 1.0000x reference)
#include <cuda_runtime.h>
#include <cuda_bf16.h>
#include <cstdint>

// ---------------------------------------------------------------------------
// OnlineLSTM: xg = inp @ W_ih^T + b_ih  (big GEMM, precomputed)
//             2048 sequential LSTM steps (persistent grid-resident kernel)
//             out = tanh(h_fin @ fc_w^T + fc_b); h_last/c_last at step 1023
// ---------------------------------------------------------------------------

#define WINDOW  2048
#define ISZ     4096
#define HID     1024
#define GATE4   4096      // 4*HID
#define METRIC  32
#define NCTA    128       // persistent CTAs for recurrence
#define UPB     8         // hidden units per CTA (NCTA*UPB = HID)

// Scratch (no cudaMalloc allowed)
__device__ float g_xg[WINDOW * GATE4];          // 32 MB
__device__ float g_h[2][HID];
__device__ volatile int g_flags[NCTA];

// ===========================================================================
// GEMM: C[t][r] = sum_k inp[t][k] * W_ih[r][k] + b_ih[r]
// 128x128 tile, K-tile 8, 256 threads, 8x8 micro-tile via fma.rn.f32x2
// ===========================================================================
#define BM 128
#define BN 128
#define BK 8
#define LDT (BM + 4)   // 132 floats, 528B row stride (16B multiple)

__device__ __forceinline__ unsigned long long dup_f32x2(float a) {
    unsigned long long r;
    unsigned int ai = __float_as_uint(a);
    asm("mov.b64 %0, {%1, %1};" : "=l"(r) : "r"(ai));
    return r;
}
__device__ __forceinline__ void fma2(unsigned long long& acc,
                                     unsigned long long a,
                                     unsigned long long b) {
    asm("fma.rn.f32x2 %0, %1, %2, %0;" : "+l"(acc) : "l"(a), "l"(b));
}

__global__ void __launch_bounds__(256) gemm_xg_kernel(
    const float* __restrict__ A,      // inp [2048,4096]
    const float* __restrict__ B,      // W_ih [4096,4096] (row = out gate, K contiguous)
    const float* __restrict__ bias,   // b_ih [4096]
    float* __restrict__ C)            // g_xg [2048,4096]
{
    __shared__ __align__(16) float As[BK][LDT];
    __shared__ __align__(16) float Bs[BK][LDT];

    const int tid = threadIdx.x;
    const int bm = blockIdx.y * BM;
    const int bn = blockIdx.x * BN;

    const int lr = tid >> 1;          // 0..127 row within tile
    const int lk = (tid & 1) * 4;     // 0 or 4
    const float* Aptr = A + (size_t)(bm + lr) * ISZ + lk;
    const float* Bptr = B + (size_t)(bn + lr) * ISZ + lk;

    const int tx = tid & 15;          // n dim
    const int ty = tid >> 4;          // m dim

    unsigned long long acc2[8][4];
#pragma unroll
    for (int i = 0; i < 8; i++)
#pragma unroll
        for (int j = 0; j < 4; j++) acc2[i][j] = 0ull;

    float4 av = *(const float4*)(Aptr);
    float4 bv = *(const float4*)(Bptr);

    for (int k0 = 0; k0 < ISZ; k0 += BK) {
        __syncthreads();
        As[lk + 0][lr] = av.x; As[lk + 1][lr] = av.y;
        As[lk + 2][lr] = av.z; As[lk + 3][lr] = av.w;
        Bs[lk + 0][lr] = bv.x; Bs[lk + 1][lr] = bv.y;
        Bs[lk + 2][lr] = bv.z; Bs[lk + 3][lr] = bv.w;
        __syncthreads();

        if (k0 + BK < ISZ) {
            av = *(const float4*)(Aptr + k0 + BK);
            bv = *(const float4*)(Bptr + k0 + BK);
        }

#pragma unroll
        for (int kk = 0; kk < BK; kk++) {
            float4 a0 = *(const float4*)&As[kk][ty * 8];
            float4 a1 = *(const float4*)&As[kk][ty * 8 + 4];
            ulonglong2 bq0 = *(const ulonglong2*)&Bs[kk][tx * 8];
            ulonglong2 bq1 = *(const ulonglong2*)&Bs[kk][tx * 8 + 4];
            unsigned long long b2[4] = {bq0.x, bq0.y, bq1.x, bq1.y};
            float a[8] = {a0.x, a0.y, a0.z, a0.w, a1.x, a1.y, a1.z, a1.w};
#pragma unroll
            for (int i = 0; i < 8; i++) {
                unsigned long long ad = dup_f32x2(a[i]);
#pragma unroll
                for (int j = 0; j < 4; j++) fma2(acc2[i][j], ad, b2[j]);
            }
        }
    }

    // epilogue: add bias, store
    float bcol[8];
#pragma unroll
    for (int j = 0; j < 8; j++) bcol[j] = bias[bn + tx * 8 + j];

#pragma unroll
    for (int i = 0; i < 8; i++) {
        float* crow = C + (size_t)(bm + ty * 8 + i) * GATE4 + bn + tx * 8;
#pragma unroll
        for (int j = 0; j < 4; j++) {
            unsigned int lo, hi;
            asm("mov.b64 {%0, %1}, %2;" : "=r"(lo), "=r"(hi) : "l"(acc2[i][j]));
            crow[2 * j]     = __uint_as_float(lo) + bcol[2 * j];
            crow[2 * j + 1] = __uint_as_float(hi) + bcol[2 * j + 1];
        }
    }
}

// ===========================================================================
// Init: reset barrier flags, seed h buffer with h1
// ===========================================================================
__global__ void init_kernel(const float* __restrict__ h1) {
    int i = threadIdx.x;   // 1024 threads
    if (i < NCTA) g_flags[i] = 0;
    g_h[0][i] = h1[i];
}

// ===========================================================================
// Persistent LSTM recurrence. 128 CTAs x 256 threads. Each CTA: 8 hidden
// units, 32 W_hh rows pinned in SMEM (128KB). Warp w owns unit (bid*8+w);
// its c lives in lane 0's register file. h exchanged via double-buffered
// global array + flag-array grid barrier (one per step).
// ===========================================================================
__device__ __forceinline__ float sigf(float x) {
    return 1.0f / (1.0f + __expf(-x));
}

__global__ void __launch_bounds__(256, 1) lstm_rec_kernel(
    const float* __restrict__ W_hh,   // [4096,1024]
    const float* __restrict__ c1,     // [1024]
    const float* __restrict__ b_hh,   // [4096]
    float* __restrict__ out,          // d_out
    int writeHC)
{
    extern __shared__ __align__(16) float smem[];
    float* Wsm = smem;                 // 32*1024 floats
    float* hsm = smem + 32 * HID;      // 1024 floats

    const int tid = threadIdx.x;
    const int bid = blockIdx.x;
    const int w = tid >> 5;            // warp id = unit within CTA
    const int l = tid & 31;
    const int j = bid * UPB + w;       // global hidden unit

    // --- stage this CTA's 32 W_hh rows into SMEM (row lr = g*8+u) ---
    for (int i = tid; i < 32 * (HID / 4); i += 256) {
        int lrow = i >> 8;             // /256 float4 per row
        int kq = i & 255;
        int g = lrow >> 3, u = lrow & 7;
        ((float4*)Wsm)[lrow * 256 + kq] =
            __ldg((const float4*)(W_hh + (size_t)(g * HID + bid * UPB + u) * HID) + kq);
    }

    float b0 = 0.f, b1 = 0.f, b2 = 0.f, b3 = 0.f, c = 0.f;
    if (l == 0) {
        b0 = b_hh[j];            b1 = b_hh[HID + j];
        b2 = b_hh[2 * HID + j];  b3 = b_hh[3 * HID + j];
        c = c1[j];
    }
    __syncthreads();

    for (int t = 0; t < WINDOW; t++) {
        const int p = t & 1;

        // broadcast h into SMEM (L2-only loads: L1 is stale inside this kernel)
        ((float4*)hsm)[tid] = __ldcg(((const float4*)g_h[p]) + tid);

        float xg0 = 0.f, xg1 = 0.f, xg2 = 0.f, xg3 = 0.f;
        if (l == 0) {
            const float* xr = g_xg + (size_t)t * GATE4 + j;
            xg0 = __ldg(xr);           xg1 = __ldg(xr + HID);
            xg2 = __ldg(xr + 2 * HID); xg3 = __ldg(xr + 3 * HID);
        }
        __syncthreads();

        float4 h4[8];
#pragma unroll
        for (int jj = 0; jj < 8; jj++) h4[jj] = ((const float4*)hsm)[l + 32 * jj];

        float acc[4] = {0.f, 0.f, 0.f, 0.f};
#pragma unroll
        for (int g = 0; g < 4; g++) {
            const float4* wr = (const float4*)(Wsm + (g * 8 + w) * HID);
#pragma unroll
            for (int jj = 0; jj < 8; jj++) {
                float4 wv = wr[l + 32 * jj];
                acc[g] += wv.x * h4[jj].x + wv.y * h4[jj].y
                        + wv.z * h4[jj].z + wv.w * h4[jj].w;
            }
        }
#pragma unroll
        for (int off = 16; off; off >>= 1) {
            acc[0] += __shfl_xor_sync(0xffffffffu, acc[0], off);
            acc[1] += __shfl_xor_sync(0xffffffffu, acc[1], off);
            acc[2] += __shfl_xor_sync(0xffffffffu, acc[2], off);
            acc[3] += __shfl_xor_sync(0xffffffffu, acc[3], off);
        }

        if (l == 0) {
            float pi = acc[0] + xg0 + b0;
            float pf = acc[1] + xg1 + b1;
            float pg = acc[2] + xg2 + b2;
            float po = acc[3] + xg3 + b3;
            float ig = sigf(pi), fg = sigf(pf), gg = tanhf(pg), og = sigf(po);
            c = fg * c + ig * gg;
            float hn = og * tanhf(c);
            g_h[p ^ 1][j] = hn;
            if (writeHC && t == 1023) {          // STRIDE-1
                out[METRIC + j] = hn;
                out[METRIC + HID + j] = c;
            }
        }
        __syncthreads();

        // ---- grid barrier (flag array, no atomics) ----
        if (tid == 0) {
            __threadfence();
            g_flags[bid] = t + 1;
        }
        if (tid < NCTA) {
            while (g_flags[tid] <= t) { }
        }
        __syncthreads();
    }
}

// ===========================================================================
// out = tanh(h_fin @ fc_w^T + fc_b). h_fin = g_h[0] (2048 even steps).
// 32 warps, one per output metric.
// ===========================================================================
__global__ void fc_kernel(const float* __restrict__ fc_w,
                          const float* __restrict__ fc_b,
                          float* __restrict__ out)
{
    const int w = threadIdx.x >> 5;    // 0..31
    const int l = threadIdx.x & 31;
    const float4* hv = (const float4*)g_h[0];
    const float4* wv = (const float4*)(fc_w + (size_t)w * HID);
    float s = 0.f;
#pragma unroll
    for (int jj = 0; jj < 8; jj++) {
        float4 a = hv[l + 32 * jj];
        float4 b = wv[l + 32 * jj];
        s += a.x * b.x + a.y * b.y + a.z * b.z + a.w * b.w;
    }
#pragma unroll
    for (int off = 16; off; off >>= 1) s += __shfl_xor_sync(0xffffffffu, s, off);
    if (l == 0) out[w] = tanhf(s + fc_b[w]);
}

// ===========================================================================
// launch
// ===========================================================================
extern "C" void kernel_launch(void* const* d_in, const int* in_sizes, int n_in,
                              void* d_out, int out_size) {
    const float* inp  = (const float*)d_in[0];
    const float* h1   = (const float*)d_in[1];
    const float* c1   = (const float*)d_in[2];
    const float* W_ih = (const float*)d_in[3];
    const float* W_hh = (const float*)d_in[4];
    // b_ih = d_in[5] used in GEMM; b_hh = d_in[6] in recurrence
    const float* b_ih = (const float*)d_in[5];
    const float* b_hh = (const float*)d_in[6];
    const float* fc_w = (const float*)d_in[7];
    const float* fc_b = (const float*)d_in[8];
    float* out = (float*)d_out;

    int writeHC = (out_size >= METRIC + 2 * HID) ? 1 : 0;

    float* xg_ptr = nullptr;
    cudaGetSymbolAddress((void**)&xg_ptr, g_xg);

    // Phase 1: xg GEMM
    dim3 ggrid(GATE4 / BN, WINDOW / BM);
    gemm_xg_kernel<<<ggrid, 256>>>(inp, W_ih, b_ih, xg_ptr);

    // Phase 1b: init h buffer + barrier flags
    init_kernel<<<1, HID>>>(h1);

    // Phase 2: persistent recurrence (128KB W + 4KB h in dynamic smem)
    size_t smem_bytes = (32 * HID + HID) * sizeof(float);
    static int attr_set = 0;
    if (!attr_set) {
        cudaFuncSetAttribute(lstm_rec_kernel,
                             cudaFuncAttributeMaxDynamicSharedMemorySize,
                             (int)smem_bytes);
        attr_set = 1;
    }
    lstm_rec_kernel<<<NCTA, 256, smem_bytes>>>(W_hh, c1, b_hh, out, writeHC);

    // Phase 3: fc epilogue
    fc_kernel<<<1, METRIC * 32>>>(fc_w, fc_b, out);
}

// round 3
// speedup vs baseline: 1.0006x; 1.0006x over previous
#include <cuda_runtime.h>
#include <cuda_bf16.h>
#include <cstdint>

// ---------------------------------------------------------------------------
// OnlineLSTM: xg = inp @ W_ih^T + b_ih  (big GEMM, precomputed)
//             2048 sequential LSTM steps (persistent grid-resident kernel)
//             out = tanh(h_fin @ fc_w^T + fc_b); h_last/c_last at step 1023
// ---------------------------------------------------------------------------

#define WINDOW  2048
#define ISZ     4096
#define HID     1024
#define GATE4   4096      // 4*HID
#define METRIC  32
#define NCTA    128       // persistent CTAs for recurrence
#define UPB     8         // hidden units per CTA (NCTA*UPB = HID)

// Scratch (no cudaMalloc allowed)
__device__ float g_xg[WINDOW * GATE4];          // 32 MB
__device__ float g_h[2][HID];
__device__ volatile int g_flags[NCTA];

// ===========================================================================
// GEMM: C[t][r] = sum_k inp[t][k] * W_ih[r][k] + b_ih[r]
// 128x128 tile, K-tile 8, 256 threads, 8x8 micro-tile via fma.rn.f32x2
// ===========================================================================
#define BM 128
#define BN 128
#define BK 8
#define LDT (BM + 4)   // 132 floats, 528B row stride (16B multiple)

__device__ __forceinline__ unsigned long long dup_f32x2(float a) {
    unsigned long long r;
    unsigned int ai = __float_as_uint(a);
    asm("mov.b64 %0, {%1, %1};" : "=l"(r) : "r"(ai));
    return r;
}
__device__ __forceinline__ void fma2(unsigned long long& acc,
                                     unsigned long long a,
                                     unsigned long long b) {
    asm("fma.rn.f32x2 %0, %1, %2, %0;" : "+l"(acc) : "l"(a), "l"(b));
}

__global__ void __launch_bounds__(256) gemm_xg_kernel(
    const float* __restrict__ A,      // inp [2048,4096]
    const float* __restrict__ B,      // W_ih [4096,4096] (row = out gate, K contiguous)
    const float* __restrict__ bias,   // b_ih [4096]
    float* __restrict__ C)            // g_xg [2048,4096]
{
    __shared__ __align__(16) float As[BK][LDT];
    __shared__ __align__(16) float Bs[BK][LDT];

    const int tid = threadIdx.x;
    const int bm = blockIdx.y * BM;
    const int bn = blockIdx.x * BN;

    const int lr = tid >> 1;          // 0..127 row within tile
    const int lk = (tid & 1) * 4;     // 0 or 4
    const float* Aptr = A + (size_t)(bm + lr) * ISZ + lk;
    const float* Bptr = B + (size_t)(bn + lr) * ISZ + lk;

    const int tx = tid & 15;          // n dim
    const int ty = tid >> 4;          // m dim

    unsigned long long acc2[8][4];
#pragma unroll
    for (int i = 0; i < 8; i++)
#pragma unroll
        for (int j = 0; j < 4; j++) acc2[i][j] = 0ull;

    float4 av = *(const float4*)(Aptr);
    float4 bv = *(const float4*)(Bptr);

    for (int k0 = 0; k0 < ISZ; k0 += BK) {
        __syncthreads();
        As[lk + 0][lr] = av.x; As[lk + 1][lr] = av.y;
        As[lk + 2][lr] = av.z; As[lk + 3][lr] = av.w;
        Bs[lk + 0][lr] = bv.x; Bs[lk + 1][lr] = bv.y;
        Bs[lk + 2][lr] = bv.z; Bs[lk + 3][lr] = bv.w;
        __syncthreads();

        if (k0 + BK < ISZ) {
            av = *(const float4*)(Aptr + k0 + BK);
            bv = *(const float4*)(Bptr + k0 + BK);
        }

#pragma unroll
        for (int kk = 0; kk < BK; kk++) {
            float4 a0 = *(const float4*)&As[kk][ty * 8];
            float4 a1 = *(const float4*)&As[kk][ty * 8 + 4];
            ulonglong2 bq0 = *(const ulonglong2*)&Bs[kk][tx * 8];
            ulonglong2 bq1 = *(const ulonglong2*)&Bs[kk][tx * 8 + 4];
            unsigned long long b2[4] = {bq0.x, bq0.y, bq1.x, bq1.y};
            float a[8] = {a0.x, a0.y, a0.z, a0.w, a1.x, a1.y, a1.z, a1.w};
#pragma unroll
            for (int i = 0; i < 8; i++) {
                unsigned long long ad = dup_f32x2(a[i]);
#pragma unroll
                for (int j = 0; j < 4; j++) fma2(acc2[i][j], ad, b2[j]);
            }
        }
    }

    // epilogue: add bias, store
    float bcol[8];
#pragma unroll
    for (int j = 0; j < 8; j++) bcol[j] = bias[bn + tx * 8 + j];

#pragma unroll
    for (int i = 0; i < 8; i++) {
        float* crow = C + (size_t)(bm + ty * 8 + i) * GATE4 + bn + tx * 8;
#pragma unroll
        for (int j = 0; j < 4; j++) {
            unsigned int lo, hi;
            asm("mov.b64 {%0, %1}, %2;" : "=r"(lo), "=r"(hi) : "l"(acc2[i][j]));
            crow[2 * j]     = __uint_as_float(lo) + bcol[2 * j];
            crow[2 * j + 1] = __uint_as_float(hi) + bcol[2 * j + 1];
        }
    }
}

// ===========================================================================
// Init: reset barrier flags, seed h buffer with h1
// ===========================================================================
__global__ void init_kernel(const float* __restrict__ h1) {
    int i = threadIdx.x;   // 1024 threads
    if (i < NCTA) g_flags[i] = 0;
    g_h[0][i] = h1[i];
}

// ===========================================================================
// Persistent LSTM recurrence. 128 CTAs x 256 threads. Each CTA: 8 hidden
// units, 32 W_hh rows pinned in SMEM (128KB). Warp w owns unit (bid*8+w);
// its c lives in lane 0's register file. h exchanged via double-buffered
// global array + flag-array grid barrier (one per step).
// ===========================================================================
__device__ __forceinline__ float sigf(float x) {
    return 1.0f / (1.0f + __expf(-x));
}

__global__ void __launch_bounds__(256, 1) lstm_rec_kernel(
    const float* __restrict__ W_hh,   // [4096,1024]
    const float* __restrict__ c1,     // [1024]
    const float* __restrict__ b_hh,   // [4096]
    float* __restrict__ out,          // d_out
    int writeHC)
{
    extern __shared__ __align__(16) float smem[];
    float* Wsm = smem;                 // 32*1024 floats
    float* hsm = smem + 32 * HID;      // 1024 floats

    const int tid = threadIdx.x;
    const int bid = blockIdx.x;
    const int w = tid >> 5;            // warp id = unit within CTA
    const int l = tid & 31;
    const int j = bid * UPB + w;       // global hidden unit

    // --- stage this CTA's 32 W_hh rows into SMEM (row lr = g*8+u) ---
    for (int i = tid; i < 32 * (HID / 4); i += 256) {
        int lrow = i >> 8;             // /256 float4 per row
        int kq = i & 255;
        int g = lrow >> 3, u = lrow & 7;
        ((float4*)Wsm)[lrow * 256 + kq] =
            __ldg((const float4*)(W_hh + (size_t)(g * HID + bid * UPB + u) * HID) + kq);
    }

    float b0 = 0.f, b1 = 0.f, b2 = 0.f, b3 = 0.f, c = 0.f;
    if (l == 0) {
        b0 = b_hh[j];            b1 = b_hh[HID + j];
        b2 = b_hh[2 * HID + j];  b3 = b_hh[3 * HID + j];
        c = c1[j];
    }
    __syncthreads();

    for (int t = 0; t < WINDOW; t++) {
        const int p = t & 1;

        // broadcast h into SMEM (L2-only loads: L1 is stale inside this kernel)
        ((float4*)hsm)[tid] = __ldcg(((const float4*)g_h[p]) + tid);

        float xg0 = 0.f, xg1 = 0.f, xg2 = 0.f, xg3 = 0.f;
        if (l == 0) {
            const float* xr = g_xg + (size_t)t * GATE4 + j;
            xg0 = __ldg(xr);           xg1 = __ldg(xr + HID);
            xg2 = __ldg(xr + 2 * HID); xg3 = __ldg(xr + 3 * HID);
        }
        __syncthreads();

        float4 h4[8];
#pragma unroll
        for (int jj = 0; jj < 8; jj++) h4[jj] = ((const float4*)hsm)[l + 32 * jj];

        float acc[4] = {0.f, 0.f, 0.f, 0.f};
#pragma unroll
        for (int g = 0; g < 4; g++) {
            const float4* wr = (const float4*)(Wsm + (g * 8 + w) * HID);
#pragma unroll
            for (int jj = 0; jj < 8; jj++) {
                float4 wv = wr[l + 32 * jj];
                acc[g] += wv.x * h4[jj].x + wv.y * h4[jj].y
                        + wv.z * h4[jj].z + wv.w * h4[jj].w;
            }
        }
#pragma unroll
        for (int off = 16; off; off >>= 1) {
            acc[0] += __shfl_xor_sync(0xffffffffu, acc[0], off);
            acc[1] += __shfl_xor_sync(0xffffffffu, acc[1], off);
            acc[2] += __shfl_xor_sync(0xffffffffu, acc[2], off);
            acc[3] += __shfl_xor_sync(0xffffffffu, acc[3], off);
        }

        if (l == 0) {
            float pi = acc[0] + xg0 + b0;
            float pf = acc[1] + xg1 + b1;
            float pg = acc[2] + xg2 + b2;
            float po = acc[3] + xg3 + b3;
            float ig = sigf(pi), fg = sigf(pf), gg = tanhf(pg), og = sigf(po);
            c = fg * c + ig * gg;
            float hn = og * tanhf(c);
            g_h[p ^ 1][j] = hn;
            if (writeHC && t == 1023) {          // STRIDE-1
                out[METRIC + j] = hn;
                out[METRIC + HID + j] = c;
            }
        }
        __syncthreads();

        // ---- grid barrier (flag array, no atomics) ----
        if (tid == 0) {
            __threadfence();
            g_flags[bid] = t + 1;
        }
        if (tid < NCTA) {
            while (g_flags[tid] <= t) { }
        }
        __syncthreads();
    }
}

// ===========================================================================
// out = tanh(h_fin @ fc_w^T + fc_b). h_fin = g_h[0] (2048 even steps).
// 32 warps, one per output metric.
// ===========================================================================
__global__ void fc_kernel(const float* __restrict__ fc_w,
                          const float* __restrict__ fc_b,
                          float* __restrict__ out)
{
    const int w = threadIdx.x >> 5;    // 0..31
    const int l = threadIdx.x & 31;
    const float4* hv = (const float4*)g_h[0];
    const float4* wv = (const float4*)(fc_w + (size_t)w * HID);
    float s = 0.f;
#pragma unroll
    for (int jj = 0; jj < 8; jj++) {
        float4 a = hv[l + 32 * jj];
        float4 b = wv[l + 32 * jj];
        s += a.x * b.x + a.y * b.y + a.z * b.z + a.w * b.w;
    }
#pragma unroll
    for (int off = 16; off; off >>= 1) s += __shfl_xor_sync(0xffffffffu, s, off);
    if (l == 0) out[w] = tanhf(s + fc_b[w]);
}

// ===========================================================================
// launch
// ===========================================================================
extern "C" void kernel_launch(void* const* d_in, const int* in_sizes, int n_in,
                              void* d_out, int out_size) {
    const float* inp  = (const float*)d_in[0];
    const float* h1   = (const float*)d_in[1];
    const float* c1   = (const float*)d_in[2];
    const float* W_ih = (const float*)d_in[3];
    const float* W_hh = (const float*)d_in[4];
    // b_ih = d_in[5] used in GEMM; b_hh = d_in[6] in recurrence
    const float* b_ih = (const float*)d_in[5];
    const float* b_hh = (const float*)d_in[6];
    const float* fc_w = (const float*)d_in[7];
    const float* fc_b = (const float*)d_in[8];
    float* out = (float*)d_out;

    int writeHC = (out_size >= METRIC + 2 * HID) ? 1 : 0;

    float* xg_ptr = nullptr;
    cudaGetSymbolAddress((void**)&xg_ptr, g_xg);

    // Phase 1: xg GEMM
    dim3 ggrid(GATE4 / BN, WINDOW / BM);
    gemm_xg_kernel<<<ggrid, 256>>>(inp, W_ih, b_ih, xg_ptr);

    // Phase 1b: init h buffer + barrier flags
    init_kernel<<<1, HID>>>(h1);

    // Phase 2: persistent recurrence (128KB W + 4KB h in dynamic smem)
    size_t smem_bytes = (32 * HID + HID) * sizeof(float);
    static int attr_set = 0;
    if (!attr_set) {
        cudaFuncSetAttribute(lstm_rec_kernel,
                             cudaFuncAttributeMaxDynamicSharedMemorySize,
                             (int)smem_bytes);
        attr_set = 1;
    }
    lstm_rec_kernel<<<NCTA, 256, smem_bytes>>>(W_hh, c1, b_hh, out, writeHC);

    // Phase 3: fc epilogue
    fc_kernel<<<1, METRIC * 32>>>(fc_w, fc_b, out);
}

// round 4
// speedup vs baseline: 2.5580x; 2.5564x over previous
#include <cuda_runtime.h>
#include <cuda_bf16.h>
#include <cstdint>

// ---------------------------------------------------------------------------
// OnlineLSTM: xg = inp @ W_ih^T + b_ih  (big GEMM, precomputed)
//             2048 sequential LSTM steps (persistent grid-resident kernel,
//             single-counter release/acquire grid barrier)
//             out = tanh(h_fin @ fc_w^T + fc_b); h_last/c_last at step 1023
// ---------------------------------------------------------------------------

#define WINDOW  2048
#define ISZ     4096
#define HID     1024
#define GATE4   4096      // 4*HID
#define METRIC  32
#define NCTA    128       // persistent CTAs for recurrence
#define UPB     8         // hidden units per CTA (NCTA*UPB = HID)

// Scratch (no cudaMalloc allowed)
__device__ float g_xg[WINDOW * GATE4];          // 32 MB
__device__ float g_h[2][HID];
__device__ int   g_cnt;                          // monotonic barrier counter

// ===========================================================================
// GEMM: C[t][r] = sum_k inp[t][k] * W_ih[r][k] + b_ih[r]
// 128x128 tile, K-tile 8, 256 threads, 8x8 micro-tile via fma.rn.f32x2
// ===========================================================================
#define BM 128
#define BN 128
#define BK 8
#define LDT (BM + 4)   // 132 floats, 528B row stride (16B multiple)

__device__ __forceinline__ unsigned long long dup_f32x2(float a) {
    unsigned long long r;
    unsigned int ai = __float_as_uint(a);
    asm("mov.b64 %0, {%1, %1};" : "=l"(r) : "r"(ai));
    return r;
}
__device__ __forceinline__ void fma2(unsigned long long& acc,
                                     unsigned long long a,
                                     unsigned long long b) {
    asm("fma.rn.f32x2 %0, %1, %2, %0;" : "+l"(acc) : "l"(a), "l"(b));
}

__global__ void __launch_bounds__(256, 2) gemm_xg_kernel(
    const float* __restrict__ A,      // inp [2048,4096]
    const float* __restrict__ B,      // W_ih [4096,4096] (row = out gate, K contiguous)
    const float* __restrict__ bias,   // b_ih [4096]
    float* __restrict__ C)            // g_xg [2048,4096]
{
    __shared__ __align__(16) float As[BK][LDT];
    __shared__ __align__(16) float Bs[BK][LDT];

    const int tid = threadIdx.x;
    const int bm = blockIdx.y * BM;
    const int bn = blockIdx.x * BN;

    const int lr = tid >> 1;          // 0..127 row within tile
    const int lk = (tid & 1) * 4;     // 0 or 4
    const float* Aptr = A + (size_t)(bm + lr) * ISZ + lk;
    const float* Bptr = B + (size_t)(bn + lr) * ISZ + lk;

    const int tx = tid & 15;          // n dim
    const int ty = tid >> 4;          // m dim

    unsigned long long acc2[8][4];
#pragma unroll
    for (int i = 0; i < 8; i++)
#pragma unroll
        for (int j = 0; j < 4; j++) acc2[i][j] = 0ull;

    float4 av = *(const float4*)(Aptr);
    float4 bv = *(const float4*)(Bptr);

    for (int k0 = 0; k0 < ISZ; k0 += BK) {
        __syncthreads();
        As[lk + 0][lr] = av.x; As[lk + 1][lr] = av.y;
        As[lk + 2][lr] = av.z; As[lk + 3][lr] = av.w;
        Bs[lk + 0][lr] = bv.x; Bs[lk + 1][lr] = bv.y;
        Bs[lk + 2][lr] = bv.z; Bs[lk + 3][lr] = bv.w;
        __syncthreads();

        if (k0 + BK < ISZ) {
            av = *(const float4*)(Aptr + k0 + BK);
            bv = *(const float4*)(Bptr + k0 + BK);
        }

#pragma unroll
        for (int kk = 0; kk < BK; kk++) {
            float4 a0 = *(const float4*)&As[kk][ty * 8];
            float4 a1 = *(const float4*)&As[kk][ty * 8 + 4];
            ulonglong2 bq0 = *(const ulonglong2*)&Bs[kk][tx * 8];
            ulonglong2 bq1 = *(const ulonglong2*)&Bs[kk][tx * 8 + 4];
            unsigned long long b2[4] = {bq0.x, bq0.y, bq1.x, bq1.y};
            float a[8] = {a0.x, a0.y, a0.z, a0.w, a1.x, a1.y, a1.z, a1.w};
#pragma unroll
            for (int i = 0; i < 8; i++) {
                unsigned long long ad = dup_f32x2(a[i]);
#pragma unroll
                for (int j = 0; j < 4; j++) fma2(acc2[i][j], ad, b2[j]);
            }
        }
    }

    // epilogue: add bias, store
    float bcol[8];
#pragma unroll
    for (int j = 0; j < 8; j++) bcol[j] = bias[bn + tx * 8 + j];

#pragma unroll
    for (int i = 0; i < 8; i++) {
        float* crow = C + (size_t)(bm + ty * 8 + i) * GATE4 + bn + tx * 8;
#pragma unroll
        for (int j = 0; j < 4; j++) {
            unsigned int lo, hi;
            asm("mov.b64 {%0, %1}, %2;" : "=r"(lo), "=r"(hi) : "l"(acc2[i][j]));
            crow[2 * j]     = __uint_as_float(lo) + bcol[2 * j];
            crow[2 * j + 1] = __uint_as_float(hi) + bcol[2 * j + 1];
        }
    }
}

// ===========================================================================
// Init: reset barrier counter, seed h buffer with h1
// ===========================================================================
__global__ void init_kernel(const float* __restrict__ h1) {
    int i = threadIdx.x;   // 1024 threads
    if (i == 0) g_cnt = 0;
    g_h[0][i] = h1[i];
}

// ===========================================================================
// Grid barrier primitives: single counter, release-RED arrival,
// single acquire-load poller per CTA.
// ===========================================================================
__device__ __forceinline__ void red_release_add1(int* p) {
    asm volatile("red.release.gpu.global.add.s32 [%0], 1;" :: "l"(p) : "memory");
}
__device__ __forceinline__ int ld_acquire(const int* p) {
    int v;
    asm volatile("ld.acquire.gpu.global.b32 %0, [%1];" : "=r"(v) : "l"(p) : "memory");
    return v;
}

// ===========================================================================
// Persistent LSTM recurrence. 128 CTAs x 256 threads. Each CTA: 8 hidden
// units, 32 W_hh rows pinned in SMEM (128KB). Warp w owns unit (bid*8+w);
// its c lives in lane 0's register file. h exchanged via double-buffered
// global array + single-counter grid barrier (one RED + one poller per CTA).
// xg(t+1) prefetched into registers during the barrier wait.
// ===========================================================================
__device__ __forceinline__ float sigf(float x) {
    return 1.0f / (1.0f + __expf(-x));
}

__global__ void __launch_bounds__(256, 1) lstm_rec_kernel(
    const float* __restrict__ W_hh,   // [4096,1024]
    const float* __restrict__ c1,     // [1024]
    const float* __restrict__ b_hh,   // [4096]
    float* __restrict__ out,          // d_out
    int writeHC)
{
    extern __shared__ __align__(16) float smem[];
    float* Wsm = smem;                 // 32*1024 floats
    float* hsm = smem + 32 * HID;      // 1024 floats

    const int tid = threadIdx.x;
    const int bid = blockIdx.x;
    const int w = tid >> 5;            // warp id = unit within CTA
    const int l = tid & 31;
    const int j = bid * UPB + w;       // global hidden unit

    // --- stage this CTA's 32 W_hh rows into SMEM (row lr = g*8+u) ---
    for (int i = tid; i < 32 * (HID / 4); i += 256) {
        int lrow = i >> 8;             // /256 float4 per row
        int kq = i & 255;
        int g = lrow >> 3, u = lrow & 7;
        ((float4*)Wsm)[lrow * 256 + kq] =
            __ldg((const float4*)(W_hh + (size_t)(g * HID + bid * UPB + u) * HID) + kq);
    }

    float b0 = 0.f, b1 = 0.f, b2 = 0.f, b3 = 0.f, c = 0.f;
    float xg0 = 0.f, xg1 = 0.f, xg2 = 0.f, xg3 = 0.f;
    if (l == 0) {
        b0 = b_hh[j];            b1 = b_hh[HID + j];
        b2 = b_hh[2 * HID + j];  b3 = b_hh[3 * HID + j];
        c = c1[j];
        // preload xg for t = 0
        const float* xr = g_xg + j;
        xg0 = __ldg(xr);           xg1 = __ldg(xr + HID);
        xg2 = __ldg(xr + 2 * HID); xg3 = __ldg(xr + 3 * HID);
    }
    __syncthreads();

    for (int t = 0; t < WINDOW; t++) {
        const int p = t & 1;

        // broadcast h into SMEM (L2-only loads: L1 is stale inside this kernel;
        // previous iteration's barrier guarantees g_h[p] is complete)
        ((float4*)hsm)[tid] = __ldcg(((const float4*)g_h[p]) + tid);
        __syncthreads();

        float4 h4[8];
#pragma unroll
        for (int jj = 0; jj < 8; jj++) h4[jj] = ((const float4*)hsm)[l + 32 * jj];

        float acc[4] = {0.f, 0.f, 0.f, 0.f};
#pragma unroll
        for (int g = 0; g < 4; g++) {
            const float4* wr = (const float4*)(Wsm + (g * 8 + w) * HID);
#pragma unroll
            for (int jj = 0; jj < 8; jj++) {
                float4 wv = wr[l + 32 * jj];
                acc[g] += wv.x * h4[jj].x + wv.y * h4[jj].y
                        + wv.z * h4[jj].z + wv.w * h4[jj].w;
            }
        }
#pragma unroll
        for (int off = 16; off; off >>= 1) {
            acc[0] += __shfl_xor_sync(0xffffffffu, acc[0], off);
            acc[1] += __shfl_xor_sync(0xffffffffu, acc[1], off);
            acc[2] += __shfl_xor_sync(0xffffffffu, acc[2], off);
            acc[3] += __shfl_xor_sync(0xffffffffu, acc[3], off);
        }

        if (l == 0) {
            float pi = acc[0] + xg0 + b0;
            float pf = acc[1] + xg1 + b1;
            float pg = acc[2] + xg2 + b2;
            float po = acc[3] + xg3 + b3;
            float ig = sigf(pi), fg = sigf(pf), gg = tanhf(pg), og = sigf(po);
            c = fg * c + ig * gg;
            float hn = og * tanhf(c);
            g_h[p ^ 1][j] = hn;
            if (writeHC && t == 1023) {          // STRIDE-1
                out[METRIC + j] = hn;
                out[METRIC + HID + j] = c;
            }
            // prefetch xg for t+1 — overlaps with the grid barrier below
            if (t + 1 < WINDOW) {
                const float* xr = g_xg + (size_t)(t + 1) * GATE4 + j;
                xg0 = __ldg(xr);           xg1 = __ldg(xr + HID);
                xg2 = __ldg(xr + 2 * HID); xg3 = __ldg(xr + 3 * HID);
            }
        }
        __syncthreads();

        // ---- grid barrier: one release-RED arrival + one acquire poller per CTA ----
        if (tid == 0) {
            red_release_add1(&g_cnt);
            const int target = (t + 1) * NCTA;
            while (ld_acquire(&g_cnt) < target) { }
        }
        __syncthreads();
    }
}

// ===========================================================================
// out = tanh(h_fin @ fc_w^T + fc_b). h_fin = g_h[0] (2048 even steps).
// 32 warps, one per output metric.
// ===========================================================================
__global__ void fc_kernel(const float* __restrict__ fc_w,
                          const float* __restrict__ fc_b,
                          float* __restrict__ out)
{
    const int w = threadIdx.x >> 5;    // 0..31
    const int l = threadIdx.x & 31;
    const float4* hv = (const float4*)g_h[0];
    const float4* wv = (const float4*)(fc_w + (size_t)w * HID);
    float s = 0.f;
#pragma unroll
    for (int jj = 0; jj < 8; jj++) {
        float4 a = __ldcg(hv + l + 32 * jj);
        float4 b = wv[l + 32 * jj];
        s += a.x * b.x + a.y * b.y + a.z * b.z + a.w * b.w;
    }
#pragma unroll
    for (int off = 16; off; off >>= 1) s += __shfl_xor_sync(0xffffffffu, s, off);
    if (l == 0) out[w] = tanhf(s + fc_b[w]);
}

// ===========================================================================
// launch
// ===========================================================================
extern "C" void kernel_launch(void* const* d_in, const int* in_sizes, int n_in,
                              void* d_out, int out_size) {
    const float* inp  = (const float*)d_in[0];
    const float* h1   = (const float*)d_in[1];
    const float* c1   = (const float*)d_in[2];
    const float* W_ih = (const float*)d_in[3];
    const float* W_hh = (const float*)d_in[4];
    const float* b_ih = (const float*)d_in[5];
    const float* b_hh = (const float*)d_in[6];
    const float* fc_w = (const float*)d_in[7];
    const float* fc_b = (const float*)d_in[8];
    float* out = (float*)d_out;

    int writeHC = (out_size >= METRIC + 2 * HID) ? 1 : 0;

    float* xg_ptr = nullptr;
    cudaGetSymbolAddress((void**)&xg_ptr, g_xg);

    // Phase 1: xg GEMM
    dim3 ggrid(GATE4 / BN, WINDOW / BM);
    gemm_xg_kernel<<<ggrid, 256>>>(inp, W_ih, b_ih, xg_ptr);

    // Phase 1b: init h buffer + barrier counter
    init_kernel<<<1, HID>>>(h1);

    // Phase 2: persistent recurrence (128KB W + 4KB h in dynamic smem)
    size_t smem_bytes = (32 * HID + HID) * sizeof(float);
    static int attr_set = 0;
    if (!attr_set) {
        cudaFuncSetAttribute(lstm_rec_kernel,
                             cudaFuncAttributeMaxDynamicSharedMemorySize,
                             (int)smem_bytes);
        attr_set = 1;
    }
    lstm_rec_kernel<<<NCTA, 256, smem_bytes>>>(W_hh, c1, b_hh, out, writeHC);

    // Phase 3: fc epilogue
    fc_kernel<<<1, METRIC * 32>>>(fc_w, fc_b, out);
}

// round 11
// speedup vs baseline: 2.9245x; 1.1433x over previous
#include <cuda_runtime.h>
#include <cuda_bf16.h>
#include <cstdint>

// ---------------------------------------------------------------------------
// OnlineLSTM: xg = inp @ W_ih^T + b_ih  (big GEMM, precomputed)
//             2048 sequential LSTM steps: persistent kernel,
//             W_hh in REGISTERS (round-4 compute core) +
//             round-3 PROVEN counter barrier / plain g_h handoff (verbatim)
//             out = tanh(h_fin @ fc_w^T + fc_b); h_last/c_last at step 1023
// ---------------------------------------------------------------------------

#define WINDOW  2048
#define ISZ     4096
#define HID     1024
#define GATE4   4096      // 4*HID
#define METRIC  32
#define NCTA    128       // persistent CTAs for recurrence
#define UPB     8         // hidden units per CTA (NCTA*UPB = HID)

// Scratch (no cudaMalloc allowed)
__device__ float g_xg[WINDOW * GATE4];          // 32 MB
__device__ float g_h[2][HID];
__device__ int   g_cnt;                          // monotonic barrier counter

// ===========================================================================
// GEMM: C[t][r] = sum_k inp[t][k] * W_ih[r][k] + b_ih[r]
// 128x128 tile, K-tile 8, 256 threads, 8x8 micro-tile via fma.rn.f32x2
// (unchanged from the round-3 passing kernel)
// ===========================================================================
#define BM 128
#define BN 128
#define BK 8
#define LDT (BM + 4)   // 132 floats, 528B row stride (16B multiple)

__device__ __forceinline__ unsigned long long dup_f32x2(float a) {
    unsigned long long r;
    unsigned int ai = __float_as_uint(a);
    asm("mov.b64 %0, {%1, %1};" : "=l"(r) : "r"(ai));
    return r;
}
__device__ __forceinline__ void fma2(unsigned long long& acc,
                                     unsigned long long a,
                                     unsigned long long b) {
    asm("fma.rn.f32x2 %0, %1, %2, %0;" : "+l"(acc) : "l"(a), "l"(b));
}

__global__ void __launch_bounds__(256, 2) gemm_xg_kernel(
    const float* __restrict__ A,      // inp [2048,4096]
    const float* __restrict__ B,      // W_ih [4096,4096]
    const float* __restrict__ bias,   // b_ih [4096]
    float* __restrict__ C)            // g_xg [2048,4096]
{
    __shared__ __align__(16) float As[BK][LDT];
    __shared__ __align__(16) float Bs[BK][LDT];

    const int tid = threadIdx.x;
    const int bm = blockIdx.y * BM;
    const int bn = blockIdx.x * BN;

    const int lr = tid >> 1;          // 0..127 row within tile
    const int lk = (tid & 1) * 4;     // 0 or 4
    const float* Aptr = A + (size_t)(bm + lr) * ISZ + lk;
    const float* Bptr = B + (size_t)(bn + lr) * ISZ + lk;

    const int tx = tid & 15;          // n dim
    const int ty = tid >> 4;          // m dim

    unsigned long long acc2[8][4];
#pragma unroll
    for (int i = 0; i < 8; i++)
#pragma unroll
        for (int j = 0; j < 4; j++) acc2[i][j] = 0ull;

    float4 av = *(const float4*)(Aptr);
    float4 bv = *(const float4*)(Bptr);

    for (int k0 = 0; k0 < ISZ; k0 += BK) {
        __syncthreads();
        As[lk + 0][lr] = av.x; As[lk + 1][lr] = av.y;
        As[lk + 2][lr] = av.z; As[lk + 3][lr] = av.w;
        Bs[lk + 0][lr] = bv.x; Bs[lk + 1][lr] = bv.y;
        Bs[lk + 2][lr] = bv.z; Bs[lk + 3][lr] = bv.w;
        __syncthreads();

        if (k0 + BK < ISZ) {
            av = *(const float4*)(Aptr + k0 + BK);
            bv = *(const float4*)(Bptr + k0 + BK);
        }

#pragma unroll
        for (int kk = 0; kk < BK; kk++) {
            float4 a0 = *(const float4*)&As[kk][ty * 8];
            float4 a1 = *(const float4*)&As[kk][ty * 8 + 4];
            ulonglong2 bq0 = *(const ulonglong2*)&Bs[kk][tx * 8];
            ulonglong2 bq1 = *(const ulonglong2*)&Bs[kk][tx * 8 + 4];
            unsigned long long b2[4] = {bq0.x, bq0.y, bq1.x, bq1.y};
            float a[8] = {a0.x, a0.y, a0.z, a0.w, a1.x, a1.y, a1.z, a1.w};
#pragma unroll
            for (int i = 0; i < 8; i++) {
                unsigned long long ad = dup_f32x2(a[i]);
#pragma unroll
                for (int j = 0; j < 4; j++) fma2(acc2[i][j], ad, b2[j]);
            }
        }
    }

    float bcol[8];
#pragma unroll
    for (int j = 0; j < 8; j++) bcol[j] = bias[bn + tx * 8 + j];

#pragma unroll
    for (int i = 0; i < 8; i++) {
        float* crow = C + (size_t)(bm + ty * 8 + i) * GATE4 + bn + tx * 8;
#pragma unroll
        for (int j = 0; j < 4; j++) {
            unsigned int lo, hi;
            asm("mov.b64 {%0, %1}, %2;" : "=r"(lo), "=r"(hi) : "l"(acc2[i][j]));
            crow[2 * j]     = __uint_as_float(lo) + bcol[2 * j];
            crow[2 * j + 1] = __uint_as_float(hi) + bcol[2 * j + 1];
        }
    }
}

// ===========================================================================
// Init: reset barrier counter, seed h buffer with h1 (round-3 verbatim)
// ===========================================================================
__global__ void init_kernel(const float* __restrict__ h1) {
    int i = threadIdx.x;   // 1024 threads
    if (i == 0) g_cnt = 0;
    g_h[0][i] = h1[i];
}

// ===========================================================================
// Grid barrier primitives (round-3 verbatim, proven at 1e-6):
// single counter, release-RED arrival, single acquire-load poller per CTA.
// ===========================================================================
__device__ __forceinline__ void red_release_add1(int* p) {
    asm volatile("red.release.gpu.global.add.s32 [%0], 1;" :: "l"(p) : "memory");
}
__device__ __forceinline__ int ld_acquire(const int* p) {
    int v;
    asm volatile("ld.acquire.gpu.global.b32 %0, [%1];" : "=r"(v) : "l"(p) : "memory");
    return v;
}

// ===========================================================================
// Persistent LSTM recurrence. 128 CTAs x 512 threads.
//   Inter-CTA machinery = round 3 (plain g_h floats, __ldcg fill, plain h
//   stores, counter barrier). Intra-CTA compute = register-resident W_hh:
//   CTA bid owns units bid*8..bid*8+7 -> 32 gate rows of W_hh.
//   Lane l of every warp owns row r=l: unit u=l>>2, gate g=l&3.
//   Warp w (0..15) owns columns [64w, 64w+64): 32 f32x2 weights in REGISTERS.
//   Warp 0 reduces the 16 per-warp partials, does gates, writes h.
//   Exact activations (1/(1+__expf), tanhf) — the math that passed at 1e-6.
// ===========================================================================
__device__ __forceinline__ float sig_exact(float x) {
    return 1.0f / (1.0f + __expf(-x));
}

__global__ void __launch_bounds__(512, 1) lstm_rec_kernel(
    const float* __restrict__ W_hh,   // [4096,1024]
    const float* __restrict__ c1,     // [1024]
    const float* __restrict__ b_hh,   // [4096]
    float* __restrict__ out,          // d_out
    int writeHC)
{
    __shared__ __align__(16) float hsm[HID];
    __shared__ float psum[16][33];

    const int tid = threadIdx.x;
    const int bid = blockIdx.x;
    const int w = tid >> 5;            // warp 0..15 -> column slab
    const int l = tid & 31;            // lane = row r: unit u=l>>2, gate g=l&3
    const int u = l >> 2;
    const int g = l & 3;
    const int gate_row = g * HID + bid * UPB + u;   // global W_hh row

    // ---- W slab into registers: 32 f32x2 (64 floats) per thread ----
    unsigned long long wreg[32];
    {
        const float* wp = W_hh + (size_t)gate_row * HID + w * 64;
#pragma unroll
        for (int k = 0; k < 32; k++)
            wreg[k] = *(const unsigned long long*)(wp + 2 * k);
    }

    // ---- warp-0 per-lane state: bias, xg(t=0), c (held in g==0 lanes) ----
    float bias = 0.f, xg = 0.f, c = 0.f;
    if (w == 0) {
        bias = b_hh[gate_row];
        xg   = __ldg(g_xg + gate_row);       // row t=0 of xg
        if (g == 0) c = c1[bid * UPB + u];
    }
    __syncthreads();

    for (int t = 0; t < WINDOW; t++) {
        const int p = t & 1;

        // ---- broadcast h into SMEM (L2-only loads; round-3 pattern) ----
        if (tid < 256)
            ((float4*)hsm)[tid] = __ldcg(((const float4*)g_h[p]) + tid);
        __syncthreads();

        // ---- compute: 64-col partial dot, h via uniform-broadcast LDS.64 ----
        unsigned long long acc = 0ull;
        const unsigned long long* hp = (const unsigned long long*)(hsm + w * 64);
#pragma unroll
        for (int k = 0; k < 32; k++) fma2(acc, wreg[k], hp[k]);
        {
            unsigned int lo, hi;
            asm("mov.b64 {%0, %1}, %2;" : "=r"(lo), "=r"(hi) : "l"(acc));
            psum[w][l] = __uint_as_float(lo) + __uint_as_float(hi);
        }
        __syncthreads();

        // ---- warp 0: cross-warp reduce, gates, plain h store ----
        if (w == 0) {
            float pre = xg + bias;
#pragma unroll
            for (int q = 0; q < 16; q++) pre += psum[q][l];

            float a = (g == 2) ? tanhf(pre) : sig_exact(pre);
            // gather this unit's 4 gate activations into its g==0 lane
            int base = l & ~3;
            float fg = __shfl_sync(0xffffffffu, a, base + 1);
            float gb = __shfl_sync(0xffffffffu, a, base + 2);
            float og = __shfl_sync(0xffffffffu, a, base + 3);
            if (g == 0) {
                c = fg * c + a * gb;
                float hn = og * tanhf(c);
                int jj = bid * UPB + u;
                g_h[p ^ 1][jj] = hn;                 // plain store (round 3)
                if (writeHC && t == 1023) {          // STRIDE-1
                    out[METRIC + jj] = hn;
                    out[METRIC + HID + jj] = c;
                }
            }
            // prefetch next step's xg (hides L2 latency under the barrier)
            if (t + 1 < WINDOW)
                xg = __ldg(g_xg + (size_t)(t + 1) * GATE4 + gate_row);
        }
        __syncthreads();

        // ---- grid barrier (round-3 verbatim): release-RED + acquire poll ----
        if (tid == 0) {
            red_release_add1(&g_cnt);
            const int target = (t + 1) * NCTA;
            while (ld_acquire(&g_cnt) < target) { }
        }
        __syncthreads();
    }
}

// ===========================================================================
// out = tanh(h_fin @ fc_w^T + fc_b). h_fin = g_h[0] (2048 even steps).
// (round-3 verbatim)
// ===========================================================================
__global__ void fc_kernel(const float* __restrict__ fc_w,
                          const float* __restrict__ fc_b,
                          float* __restrict__ out)
{
    const int w = threadIdx.x >> 5;    // 0..31 metric
    const int l = threadIdx.x & 31;
    const float* wv = fc_w + (size_t)w * HID;
    float s = 0.f;
#pragma unroll
    for (int jj = 0; jj < 8; jj++) {
        float4 a = __ldcg(((const float4*)g_h[0]) + l + 32 * jj);
        float4 b = ((const float4*)wv)[l + 32 * jj];
        s += a.x * b.x + a.y * b.y + a.z * b.z + a.w * b.w;
    }
#pragma unroll
    for (int off = 16; off; off >>= 1) s += __shfl_xor_sync(0xffffffffu, s, off);
    if (l == 0) out[w] = tanhf(s + fc_b[w]);
}

// ===========================================================================
// launch
// ===========================================================================
extern "C" void kernel_launch(void* const* d_in, const int* in_sizes, int n_in,
                              void* d_out, int out_size) {
    const float* inp  = (const float*)d_in[0];
    const float* h1   = (const float*)d_in[1];
    const float* c1   = (const float*)d_in[2];
    const float* W_ih = (const float*)d_in[3];
    const float* W_hh = (const float*)d_in[4];
    const float* b_ih = (const float*)d_in[5];
    const float* b_hh = (const float*)d_in[6];
    const float* fc_w = (const float*)d_in[7];
    const float* fc_b = (const float*)d_in[8];
    float* out = (float*)d_out;

    int writeHC = (out_size >= METRIC + 2 * HID) ? 1 : 0;

    float* xg_ptr = nullptr;
    cudaGetSymbolAddress((void**)&xg_ptr, g_xg);

    // Phase 1: xg GEMM
    dim3 ggrid(GATE4 / BN, WINDOW / BM);
    gemm_xg_kernel<<<ggrid, 256>>>(inp, W_ih, b_ih, xg_ptr);

    // Phase 1b: init h buffer + barrier counter
    init_kernel<<<1, HID>>>(h1);

    // Phase 2: persistent recurrence (weights in registers, ~6KB static smem)
    lstm_rec_kernel<<<NCTA, 512>>>(W_hh, c1, b_hh, out, writeHC);

    // Phase 3: fc epilogue
    fc_kernel<<<1, METRIC * 32>>>(fc_w, fc_b, out);
}